// round 7
// baseline (speedup 1.0000x reference)
#include <cuda_runtime.h>
#include <math.h>

#define B_    32
#define H_    6
#define W_    2400
#define C_    64
#define OV_   4
#define G_    3
#define NVQ_  6
#define K_    1024
#define D_    8
#define FIX_  384
#define GD_   512
#define T_    600
#define NPG   (B_*T_)              // 19200
#define NPTS  (G_*NPG)             // 57600
#define ZQ_SIZE  (B_*H_*W_*C_)     // 29491200
#define IDX_SIZE (B_*NVQ_*G_*T_)   // 345600
#define RVQ_BLOCKS 900             // 64 points per block, 128 threads

__device__ float g_en2s[G_*NVQ_*K_*D_];  // split layout [jl][q][s][pos]
__device__ float g_zd [G_*NPG*D_];
__device__ float g_zqd[G_*NPG*D_];
__device__ float g_partial[RVQ_BLOCKS];

// ---------------------------------------------------------------------------
// K1: normalize codebook rows, split layout:
// g_en2s[gi*8192 + jl*64 + (d>>1)*16 + s*4 + (d&1)*2 + half]
// ---------------------------------------------------------------------------
__global__ void k_norm(const float* __restrict__ cb) {
    int r = blockIdx.x * blockDim.x + threadIdx.x;
    if (r >= G_*NVQ_*K_) return;
    const float* src = cb + (size_t)r * D_;
    float v[8]; float ss = 0.f;
#pragma unroll
    for (int d = 0; d < 8; d++) { v[d] = src[d]; ss = fmaf(v[d], v[d], ss); }
    float inv = 1.0f / fmaxf(sqrtf(ss), 1e-12f);
    int gi = r >> 10, k = r & 1023;
    int s = k >> 8, jl = (k & 255) >> 1, half = k & 1;
    float* d2 = g_en2s + (size_t)gi*(K_*D_) + jl*64 + s*4 + half;
#pragma unroll
    for (int d = 0; d < 8; d++)
        d2[(d >> 1)*16 + (d & 1)*2] = v[d] * inv;
}

// ---------------------------------------------------------------------------
// K2: pre_process fused with proj_down (paired-h STS.64 staging).
// ---------------------------------------------------------------------------
#define SZ_STRIDE 1540
#define PD_STRIDE 520
#define K2_SMEM   ((8*SZ_STRIDE + 24*PD_STRIDE) * 4)

__global__ void k_down(const float* __restrict__ ze, const float* __restrict__ pd) {
    extern __shared__ float sm[];
    float* sZ  = sm;
    float* sPD = sm + 8*SZ_STRIDE;
    int bid  = blockIdx.x;
    int b    = bid / (T_/8);
    int tblk = bid % (T_/8);
    int t0   = tblk * 8;
    int w0   = t0 * 4;
    int tid  = threadIdx.x;

    for (int idx = tid; idx < G_*D_*GD_; idx += 256) {
        int gd = idx >> 9, j = idx & 511;
        sPD[gd*PD_STRIDE + j] = pd[idx];
    }
#pragma unroll
    for (int hp = 0; hp < 3; hp++) {
        const float* s0 = ze + ((size_t)(b*H_ + 2*hp    )*W_ + w0) * C_;
        const float* s1 = ze + ((size_t)(b*H_ + 2*hp + 1)*W_ + w0) * C_;
        for (int e = tid; e < 32*64; e += 256) {
            float v0 = s0[e], v1 = s1[e];
            int wl = e >> 6, c = e & 63;
            int tl = wl >> 2, o = wl & 3;
            *(float2*)(sZ + tl*SZ_STRIDE + o*FIX_ + c*6 + 2*hp) = make_float2(v0, v1);
        }
    }
    __syncthreads();

    if (tid < 192) {
        int gd = tid >> 3;
        int tl = tid & 7;
        int g  = gd >> 3, d = gd & 7;
        const float4* zr = (const float4*)(sZ + tl*SZ_STRIDE + g*GD_);
        const float4* pr = (const float4*)(sPD + gd*PD_STRIDE);
        float a0 = 0.f, a1 = 0.f, a2 = 0.f, a3 = 0.f;
#pragma unroll 8
        for (int j = 0; j < 128; j += 2) {
            float4 z0 = zr[j],   p0 = pr[j];
            float4 z1 = zr[j+1], p1 = pr[j+1];
            a0 = fmaf(z0.x, p0.x, a0); a1 = fmaf(z0.y, p0.y, a1);
            a2 = fmaf(z0.z, p0.z, a2); a3 = fmaf(z0.w, p0.w, a3);
            a0 = fmaf(z1.x, p1.x, a0); a1 = fmaf(z1.y, p1.y, a1);
            a2 = fmaf(z1.z, p1.z, a2); a3 = fmaf(z1.w, p1.w, a3);
        }
        g_zd[((size_t)g*NPG + b*T_ + t0 + tl)*D_ + d] = (a0 + a1) + (a2 + a3);
    }
}

// ---------------------------------------------------------------------------
// K3: residual VQ. Block = 128 threads = 32 point-slots x 4 k-splits,
// 2 points per thread -> 64 points/block, 900 blocks single-wave,
// ~24 warps/SM (2x R6) for latency hiding.
// ---------------------------------------------------------------------------
__device__ __forceinline__ int combine4(float best, int bk) {
    unsigned bits = __float_as_uint(best);
    unsigned su = bits ^ (unsigned)(((int)bits >> 31) | 0x80000000);
    unsigned long long key = ((unsigned long long)su << 10) | (unsigned)(1023 - bk);
    unsigned long long o = __shfl_xor_sync(0xffffffffu, key, 1);
    key = (o > key) ? o : key;
    o = __shfl_xor_sync(0xffffffffu, key, 2);
    key = (o > key) ? o : key;
    return 1023 - (int)(key & 1023u);
}

__global__ void __launch_bounds__(128) k_rvq(float* __restrict__ out_codes) {
    __shared__ float sE[K_*D_];   // 32 KB
    __shared__ float sWarp[4];
    int bid = blockIdx.x;
    int g   = bid / (RVQ_BLOCKS/G_);
    int lb  = bid % (RVQ_BLOCKS/G_);
    int tid = threadIdx.x;
    int slot = tid >> 2;                  // 0..31
    int s    = tid & 3;                   // split
    int pl0  = lb*64 + slot*2;
    int p0   = g*NPG + pl0;

    unsigned long long r2[2][8];
    {
        const float4* zd4 = (const float4*)g_zd;
#pragma unroll
        for (int m = 0; m < 2; m++) {
            float4 lo = zd4[(size_t)(p0+m)*2], hi = zd4[(size_t)(p0+m)*2+1];
            float rv[8] = { lo.x, lo.y, lo.z, lo.w, hi.x, hi.y, hi.z, hi.w };
#pragma unroll
            for (int d = 0; d < 8; d++)
                asm("mov.b64 %0, {%1, %1};" : "=l"(r2[m][d]) : "f"(rv[d]));
        }
    }
    int ofs[2];
#pragma unroll
    for (int m = 0; m < 2; m++) {
        int pl = pl0 + m;
        int b = pl / T_, t = pl - b*T_;
        ofs[m] = (b*NVQ_*G_ + g)*T_ + t;
    }

    float sse = 0.f;

    for (int i = 0; i < NVQ_; i++) {
        __syncthreads();
        {
            const float4* src = (const float4*)(g_en2s + (size_t)(g*NVQ_ + i)*(K_*D_));
            float4* dst = (float4*)sE;
#pragma unroll
            for (int j = 0; j < 16; j++) dst[tid + j*128] = src[tid + j*128];
        }
        __syncthreads();

        const ulonglong2* e2 = (const ulonglong2*)sE;
        float best[2] = { -3.0e38f, -3.0e38f };
        int   bj[2]   = { 0, 0 };
#pragma unroll 2
        for (int j = 0; j < 128; j++) {
            int base = j*16 + s;
            ulonglong2 c0 = e2[base];
            ulonglong2 c1 = e2[base + 4];
            ulonglong2 c2 = e2[base + 8];
            ulonglong2 c3 = e2[base + 12];
#define SIM(mm, ACC) \
            asm("mul.rn.f32x2 %0, %1, %2;"     : "=l"(ACC) : "l"(r2[mm][0]), "l"(c0.x)); \
            asm("fma.rn.f32x2 %0, %1, %2, %0;" : "+l"(ACC) : "l"(r2[mm][1]), "l"(c0.y)); \
            asm("fma.rn.f32x2 %0, %1, %2, %0;" : "+l"(ACC) : "l"(r2[mm][2]), "l"(c1.x)); \
            asm("fma.rn.f32x2 %0, %1, %2, %0;" : "+l"(ACC) : "l"(r2[mm][3]), "l"(c1.y)); \
            asm("fma.rn.f32x2 %0, %1, %2, %0;" : "+l"(ACC) : "l"(r2[mm][4]), "l"(c2.x)); \
            asm("fma.rn.f32x2 %0, %1, %2, %0;" : "+l"(ACC) : "l"(r2[mm][5]), "l"(c2.y)); \
            asm("fma.rn.f32x2 %0, %1, %2, %0;" : "+l"(ACC) : "l"(r2[mm][6]), "l"(c3.x)); \
            asm("fma.rn.f32x2 %0, %1, %2, %0;" : "+l"(ACC) : "l"(r2[mm][7]), "l"(c3.y));
            unsigned long long a0, a1;
            SIM(0, a0) SIM(1, a1)
            float lo, hi, m;
            asm("mov.b64 {%0, %1}, %2;" : "=f"(lo), "=f"(hi) : "l"(a0));
            m = fmaxf(lo, hi);
            if (m > best[0]) { best[0] = m; bj[0] = j; }
            asm("mov.b64 {%0, %1}, %2;" : "=f"(lo), "=f"(hi) : "l"(a1));
            m = fmaxf(lo, hi);
            if (m > best[1]) { best[1] = m; bj[1] = j; }
        }

        // resolve even/odd by recomputing the winning pair (same op order)
        int kk[2];
#pragma unroll
        for (int m = 0; m < 2; m++) {
            int base = bj[m]*16 + s;
            ulonglong2 c0 = e2[base];
            ulonglong2 c1 = e2[base + 4];
            ulonglong2 c2 = e2[base + 8];
            ulonglong2 c3 = e2[base + 12];
            unsigned long long a;
            if (m == 0) { SIM(0, a) } else { SIM(1, a) }
            float lo, hi;
            asm("mov.b64 {%0, %1}, %2;" : "=f"(lo), "=f"(hi) : "l"(a));
            int kc = s*256 + 2*bj[m] + ((hi > lo) ? 1 : 0);
            kk[m] = combine4(best[m], kc);
        }
#undef SIM

        // gather chosen codeword from smem + update residual
#pragma unroll
        for (int m = 0; m < 2; m++) {
            int k = kk[m];
            int base = ((k & 255) >> 1)*64 + ((k >> 8) << 2) + (k & 1);
            float ss = 0.f;
#pragma unroll
            for (int d = 0; d < 8; d++) {
                float ev = sE[base + (d >> 1)*16 + (d & 1)*2];
                float rlo;
                asm("mov.b64 {%0, _}, %1;" : "=f"(rlo) : "l"(r2[m][d]));
                float rn = rlo - ev;
                asm("mov.b64 %0, {%1, %1};" : "=l"(r2[m][d]) : "f"(rn));
                ss = fmaf(rn, rn, ss);
            }
            sse += ss;
        }
        if (s == 0) {
            float* oc = out_codes + (size_t)i*(G_*T_);
            oc[ofs[0]] = (float)kk[0];
            oc[ofs[1]] = (float)kk[1];
        }
    }

    if (s == 0) {
        const float4* zd4 = (const float4*)g_zd;
        float4* zq4 = (float4*)g_zqd;
#pragma unroll
        for (int m = 0; m < 2; m++) {
            float4 lo = zd4[(size_t)(p0+m)*2], hi = zd4[(size_t)(p0+m)*2+1];
            float zv[8] = { lo.x, lo.y, lo.z, lo.w, hi.x, hi.y, hi.z, hi.w };
            float qv[8];
#pragma unroll
            for (int d = 0; d < 8; d++) {
                float rlo;
                asm("mov.b64 {%0, _}, %1;" : "=f"(rlo) : "l"(r2[m][d]));
                qv[d] = zv[d] - rlo;
            }
            zq4[(size_t)(p0+m)*2]   = make_float4(qv[0], qv[1], qv[2], qv[3]);
            zq4[(size_t)(p0+m)*2+1] = make_float4(qv[4], qv[5], qv[6], qv[7]);
        }
    }

    float c = (s == 0) ? sse : 0.f;
#pragma unroll
    for (int off = 16; off > 0; off >>= 1)
        c += __shfl_down_sync(0xffffffffu, c, off);
    int lane = tid & 31, wid = tid >> 5;
    if (lane == 0) sWarp[wid] = c;
    __syncthreads();
    if (tid == 0)
        g_partial[bid] = (sWarp[0] + sWarp[1]) + (sWarp[2] + sWarp[3]);
}

// ---------------------------------------------------------------------------
// K4: proj_up fused with post_process (R5 version: 1 c per thread, 33us).
// ---------------------------------------------------------------------------
#define TT 25
__global__ void __launch_bounds__(256) k_up(const float* __restrict__ pu, float* __restrict__ out) {
    __shared__ float sZ[G_*TT*D_];
    int bid  = blockIdx.x;
    int b    = bid / (T_/TT);
    int tile = bid % (T_/TT);
    int t0   = tile * TT;
    int tid  = threadIdx.x;

    for (int idx = tid; idx < G_*TT*D_; idx += 256) {
        int g  = idx / (TT*D_);
        int rr = idx % (TT*D_);
        sZ[idx] = g_zqd[((size_t)g*NPG + b*T_ + t0)*D_ + rr];
    }
    __syncthreads();

    int wid = tid >> 5, lane = tid & 31;
    for (int task = wid; task < 48; task += 8) {
        int o   = task / 12;
        int rem = task % 12;
        int h   = rem >> 1;
        int ch  = rem & 1;
        int c   = ch*32 + lane;
        int pp  = o*FIX_ + c*6 + h;
        int g   = pp >> 9;
        const float4* pu4 = (const float4*)pu + (size_t)pp*2;
        float4 pl = __ldg(pu4), ph = __ldg(pu4 + 1);
        float* op = out + ((size_t)(b*H_ + h)*W_ + 4*t0 + o)*C_ + c;
        const float4* zb = (const float4*)(sZ + g*(TT*D_));
#pragma unroll 5
        for (int tl = 0; tl < TT; tl++) {
            float4 zl = zb[tl*2], zh = zb[tl*2 + 1];
            float s0 = zl.x*pl.x, s1 = zl.y*pl.y;
            s0 = fmaf(zl.z, pl.z, s0); s1 = fmaf(zl.w, pl.w, s1);
            s0 = fmaf(zh.x, ph.x, s0); s1 = fmaf(zh.y, ph.y, s1);
            s0 = fmaf(zh.z, ph.z, s0); s1 = fmaf(zh.w, ph.w, s1);
            op[(size_t)tl*4*C_] = s0 + s1;
        }
    }
}

// ---------------------------------------------------------------------------
// K5: final deterministic loss reduction.
// ---------------------------------------------------------------------------
__global__ void k_final(float* __restrict__ d_out) {
    __shared__ float s[512];
    int tid = threadIdx.x;
    float v = 0.f;
    for (int idx = tid; idx < RVQ_BLOCKS; idx += 512) v += g_partial[idx];
    s[tid] = v; __syncthreads();
    for (int off = 256; off > 0; off >>= 1) {
        if (tid < off) s[tid] += s[tid + off];
        __syncthreads();
    }
    if (tid == 0) {
        float loss = s[0] / (float)(G_ * B_ * T_ * D_);
        d_out[ZQ_SIZE + IDX_SIZE]     = loss;
        d_out[ZQ_SIZE + IDX_SIZE + 1] = loss;
    }
}

// ---------------------------------------------------------------------------
extern "C" void kernel_launch(void* const* d_in, const int* in_sizes, int n_in,
                              void* d_out, int out_size) {
    const float* z_e = (const float*)d_in[0];
    const float* pd  = (const float*)d_in[1];
    const float* pu  = (const float*)d_in[2];
    const float* cb  = (const float*)d_in[3];
    float* out = (float*)d_out;

    cudaFuncSetAttribute(k_down, cudaFuncAttributeMaxDynamicSharedMemorySize, K2_SMEM);

    k_norm<<<(G_*NVQ_*K_ + 255)/256, 256>>>(cb);
    k_down<<<B_*(T_/8), 256, K2_SMEM>>>(z_e, pd);
    k_rvq<<<RVQ_BLOCKS, 128>>>(out + ZQ_SIZE);
    k_up<<<B_*(T_/TT), 256>>>(pu, out);
    k_final<<<1, 512>>>(out);
}

// round 8
// speedup vs baseline: 1.0182x; 1.0182x over previous
#include <cuda_runtime.h>
#include <math.h>

#define B_    32
#define H_    6
#define W_    2400
#define C_    64
#define OV_   4
#define G_    3
#define NVQ_  6
#define K_    1024
#define D_    8
#define FIX_  384
#define GD_   512
#define T_    600
#define NPG   (B_*T_)              // 19200
#define NPTS  (G_*NPG)             // 57600
#define ZQ_SIZE  (B_*H_*W_*C_)     // 29491200
#define IDX_SIZE (B_*NVQ_*G_*T_)   // 345600
#define RVQ_BLOCKS 900             // 64 points per block, 32 threads

__device__ float g_en2s[G_*NVQ_*K_*D_];  // split layout [jl][q][s][pos]
__device__ float g_zd [G_*NPG*D_];
__device__ float g_zqd[G_*NPG*D_];
__device__ float g_partial[RVQ_BLOCKS];

// ---------------------------------------------------------------------------
// K1: normalize codebook rows, split layout:
// g_en2s[gi*8192 + jl*64 + (d>>1)*16 + s*4 + (d&1)*2 + half]
// ---------------------------------------------------------------------------
__global__ void k_norm(const float* __restrict__ cb) {
    int r = blockIdx.x * blockDim.x + threadIdx.x;
    if (r >= G_*NVQ_*K_) return;
    const float* src = cb + (size_t)r * D_;
    float v[8]; float ss = 0.f;
#pragma unroll
    for (int d = 0; d < 8; d++) { v[d] = src[d]; ss = fmaf(v[d], v[d], ss); }
    float inv = 1.0f / fmaxf(sqrtf(ss), 1e-12f);
    int gi = r >> 10, k = r & 1023;
    int s = k >> 8, jl = (k & 255) >> 1, half = k & 1;
    float* d2 = g_en2s + (size_t)gi*(K_*D_) + jl*64 + s*4 + half;
#pragma unroll
    for (int d = 0; d < 8; d++)
        d2[(d >> 1)*16 + (d & 1)*2] = v[d] * inv;
}

// ---------------------------------------------------------------------------
// K2: pre_process fused with proj_down (R5 float4 staging).
// ---------------------------------------------------------------------------
#define SZ_STRIDE 1540
#define PD_STRIDE 520
#define K2_SMEM   ((8*SZ_STRIDE + 24*PD_STRIDE) * 4)

__global__ void k_down(const float* __restrict__ ze, const float* __restrict__ pd) {
    extern __shared__ float sm[];
    float* sZ  = sm;
    float* sPD = sm + 8*SZ_STRIDE;
    int bid  = blockIdx.x;
    int b    = bid / (T_/8);
    int tblk = bid % (T_/8);
    int t0   = tblk * 8;
    int w0   = t0 * 4;
    int tid  = threadIdx.x;

    for (int idx = tid; idx < G_*D_*GD_; idx += 256) {
        int gd = idx >> 9, j = idx & 511;
        sPD[gd*PD_STRIDE + j] = pd[idx];
    }
#pragma unroll
    for (int h = 0; h < 6; h++) {
        const float4* src = (const float4*)(ze + ((size_t)(b*H_ + h)*W_ + w0) * C_);
        for (int e4 = tid; e4 < 32*16; e4 += 256) {
            float4 zv = src[e4];
            int e  = e4 * 4;
            int wl = e >> 6, c = e & 63;
            int tl = wl >> 2, o = wl & 3;
            float* dst = sZ + tl*SZ_STRIDE + o*FIX_ + c*6 + h;
            dst[0]  = zv.x; dst[6]  = zv.y;
            dst[12] = zv.z; dst[18] = zv.w;
        }
    }
    __syncthreads();

    if (tid < 192) {
        int gd = tid >> 3;
        int tl = tid & 7;
        int g  = gd >> 3, d = gd & 7;
        const float4* zr = (const float4*)(sZ + tl*SZ_STRIDE + g*GD_);
        const float4* pr = (const float4*)(sPD + gd*PD_STRIDE);
        float a0 = 0.f, a1 = 0.f, a2 = 0.f, a3 = 0.f;
#pragma unroll 8
        for (int j = 0; j < 128; j += 2) {
            float4 z0 = zr[j],   p0 = pr[j];
            float4 z1 = zr[j+1], p1 = pr[j+1];
            a0 = fmaf(z0.x, p0.x, a0); a1 = fmaf(z0.y, p0.y, a1);
            a2 = fmaf(z0.z, p0.z, a2); a3 = fmaf(z0.w, p0.w, a3);
            a0 = fmaf(z1.x, p1.x, a0); a1 = fmaf(z1.y, p1.y, a1);
            a2 = fmaf(z1.z, p1.z, a2); a3 = fmaf(z1.w, p1.w, a3);
        }
        g_zd[((size_t)g*NPG + b*T_ + t0 + tl)*D_ + d] = (a0 + a1) + (a2 + a3);
    }
}

// ---------------------------------------------------------------------------
// K3: residual VQ. Block = 32 threads = 8 point-slots x 4 k-splits,
// 8 points per thread -> 64 points/block, 900 balanced blocks.
// One 64B codebook chunk feeds 8 accumulator chains (min LDS per point-cw).
// Warp-level syncs only. Deferred even/odd parity resolution.
// ---------------------------------------------------------------------------
__device__ __forceinline__ int combine4(float best, int bk) {
    unsigned bits = __float_as_uint(best);
    unsigned su = bits ^ (unsigned)(((int)bits >> 31) | 0x80000000);
    unsigned long long key = ((unsigned long long)su << 10) | (unsigned)(1023 - bk);
    unsigned long long o = __shfl_xor_sync(0xffffffffu, key, 1);
    key = (o > key) ? o : key;
    o = __shfl_xor_sync(0xffffffffu, key, 2);
    key = (o > key) ? o : key;
    return 1023 - (int)(key & 1023u);
}

__global__ void __launch_bounds__(32) k_rvq(float* __restrict__ out_codes) {
    __shared__ float sE[K_*D_];   // 32 KB
    int bid  = blockIdx.x;
    int g    = bid / (RVQ_BLOCKS/G_);
    int lb   = bid % (RVQ_BLOCKS/G_);
    int tid  = threadIdx.x;
    int slot = tid >> 2;                  // 0..7
    int s    = tid & 3;                   // split
    int pl0  = lb*64 + slot*8;
    int p0   = g*NPG + pl0;

    unsigned long long r2[8][8];
    {
        const float4* zd4 = (const float4*)g_zd;
#pragma unroll
        for (int m = 0; m < 8; m++) {
            float4 lo = zd4[(size_t)(p0+m)*2], hi = zd4[(size_t)(p0+m)*2+1];
            float rv[8] = { lo.x, lo.y, lo.z, lo.w, hi.x, hi.y, hi.z, hi.w };
#pragma unroll
            for (int d = 0; d < 8; d++)
                asm("mov.b64 %0, {%1, %1};" : "=l"(r2[m][d]) : "f"(rv[d]));
        }
    }
    int ofs[8];
#pragma unroll
    for (int m = 0; m < 8; m++) {
        int pl = pl0 + m;
        int b = pl / T_, t = pl - b*T_;
        ofs[m] = (b*NVQ_*G_ + g)*T_ + t;
    }

    float sse = 0.f;

    for (int i = 0; i < NVQ_; i++) {
        __syncwarp();
        {
            const float4* src = (const float4*)(g_en2s + (size_t)(g*NVQ_ + i)*(K_*D_));
            float4* dst = (float4*)sE;
#pragma unroll
            for (int j = 0; j < 64; j++) dst[tid + j*32] = src[tid + j*32];
        }
        __syncwarp();

        const ulonglong2* e2 = (const ulonglong2*)sE;
        float best[8];
        int   bj[8];
#pragma unroll
        for (int m = 0; m < 8; m++) { best[m] = -3.0e38f; bj[m] = 0; }

        for (int j = 0; j < 128; j++) {
            int base = j*16 + s;
            ulonglong2 c0 = e2[base];
            ulonglong2 c1 = e2[base + 4];
            ulonglong2 c2 = e2[base + 8];
            ulonglong2 c3 = e2[base + 12];
#define SIM(mm, ACC) \
            asm("mul.rn.f32x2 %0, %1, %2;"     : "=l"(ACC) : "l"(r2[mm][0]), "l"(c0.x)); \
            asm("fma.rn.f32x2 %0, %1, %2, %0;" : "+l"(ACC) : "l"(r2[mm][1]), "l"(c0.y)); \
            asm("fma.rn.f32x2 %0, %1, %2, %0;" : "+l"(ACC) : "l"(r2[mm][2]), "l"(c1.x)); \
            asm("fma.rn.f32x2 %0, %1, %2, %0;" : "+l"(ACC) : "l"(r2[mm][3]), "l"(c1.y)); \
            asm("fma.rn.f32x2 %0, %1, %2, %0;" : "+l"(ACC) : "l"(r2[mm][4]), "l"(c2.x)); \
            asm("fma.rn.f32x2 %0, %1, %2, %0;" : "+l"(ACC) : "l"(r2[mm][5]), "l"(c2.y)); \
            asm("fma.rn.f32x2 %0, %1, %2, %0;" : "+l"(ACC) : "l"(r2[mm][6]), "l"(c3.x)); \
            asm("fma.rn.f32x2 %0, %1, %2, %0;" : "+l"(ACC) : "l"(r2[mm][7]), "l"(c3.y));
            unsigned long long a0, a1, a2, a3, a4, a5, a6, a7;
            SIM(0, a0) SIM(1, a1) SIM(2, a2) SIM(3, a3)
            SIM(4, a4) SIM(5, a5) SIM(6, a6) SIM(7, a7)
            float lo, hi, m;
#define CMP(mm, ACC) \
            asm("mov.b64 {%0, %1}, %2;" : "=f"(lo), "=f"(hi) : "l"(ACC)); \
            m = fmaxf(lo, hi); \
            if (m > best[mm]) { best[mm] = m; bj[mm] = j; }
            CMP(0, a0) CMP(1, a1) CMP(2, a2) CMP(3, a3)
            CMP(4, a4) CMP(5, a5) CMP(6, a6) CMP(7, a7)
#undef CMP
        }

        // resolve even/odd by recomputing the winning pair (same op order)
        int kk[8];
#pragma unroll
        for (int m = 0; m < 8; m++) {
            int base = bj[m]*16 + s;
            ulonglong2 c0 = e2[base];
            ulonglong2 c1 = e2[base + 4];
            ulonglong2 c2 = e2[base + 8];
            ulonglong2 c3 = e2[base + 12];
            unsigned long long a;
            switch (m) {
                case 0: { SIM(0, a) } break;
                case 1: { SIM(1, a) } break;
                case 2: { SIM(2, a) } break;
                case 3: { SIM(3, a) } break;
                case 4: { SIM(4, a) } break;
                case 5: { SIM(5, a) } break;
                case 6: { SIM(6, a) } break;
                default:{ SIM(7, a) } break;
            }
            float lo, hi;
            asm("mov.b64 {%0, %1}, %2;" : "=f"(lo), "=f"(hi) : "l"(a));
            int kc = s*256 + 2*bj[m] + ((hi > lo) ? 1 : 0);
            kk[m] = combine4(best[m], kc);
        }
#undef SIM

        // gather chosen codeword from smem + update residual
#pragma unroll
        for (int m = 0; m < 8; m++) {
            int k = kk[m];
            int base = ((k & 255) >> 1)*64 + ((k >> 8) << 2) + (k & 1);
            float ss = 0.f;
#pragma unroll
            for (int d = 0; d < 8; d++) {
                float ev = sE[base + (d >> 1)*16 + (d & 1)*2];
                float rlo;
                asm("mov.b64 {%0, _}, %1;" : "=f"(rlo) : "l"(r2[m][d]));
                float rn = rlo - ev;
                asm("mov.b64 %0, {%1, %1};" : "=l"(r2[m][d]) : "f"(rn));
                ss = fmaf(rn, rn, ss);
            }
            sse += ss;
        }
        if (s == 0) {
            float* oc = out_codes + (size_t)i*(G_*T_);
#pragma unroll
            for (int m = 0; m < 8; m++) oc[ofs[m]] = (float)kk[m];
        }
    }

    // q = zd - r_final; write zqd
    if (s == 0) {
        const float4* zd4 = (const float4*)g_zd;
        float4* zq4 = (float4*)g_zqd;
#pragma unroll
        for (int m = 0; m < 8; m++) {
            float4 lo = zd4[(size_t)(p0+m)*2], hi = zd4[(size_t)(p0+m)*2+1];
            float zv[8] = { lo.x, lo.y, lo.z, lo.w, hi.x, hi.y, hi.z, hi.w };
            float qv[8];
#pragma unroll
            for (int d = 0; d < 8; d++) {
                float rlo;
                asm("mov.b64 {%0, _}, %1;" : "=f"(rlo) : "l"(r2[m][d]));
                qv[d] = zv[d] - rlo;
            }
            zq4[(size_t)(p0+m)*2]   = make_float4(qv[0], qv[1], qv[2], qv[3]);
            zq4[(size_t)(p0+m)*2+1] = make_float4(qv[4], qv[5], qv[6], qv[7]);
        }
    }

    // deterministic warp reduction of sse (count each point once: s==0)
    float c = (s == 0) ? sse : 0.f;
#pragma unroll
    for (int off = 16; off > 0; off >>= 1)
        c += __shfl_down_sync(0xffffffffu, c, off);
    if (tid == 0) g_partial[bid] = c;
}

// ---------------------------------------------------------------------------
// K4: proj_up fused with post_process (R5 version).
// ---------------------------------------------------------------------------
#define TT 25
__global__ void __launch_bounds__(256) k_up(const float* __restrict__ pu, float* __restrict__ out) {
    __shared__ float sZ[G_*TT*D_];
    int bid  = blockIdx.x;
    int b    = bid / (T_/TT);
    int tile = bid % (T_/TT);
    int t0   = tile * TT;
    int tid  = threadIdx.x;

    for (int idx = tid; idx < G_*TT*D_; idx += 256) {
        int g  = idx / (TT*D_);
        int rr = idx % (TT*D_);
        sZ[idx] = g_zqd[((size_t)g*NPG + b*T_ + t0)*D_ + rr];
    }
    __syncthreads();

    int wid = tid >> 5, lane = tid & 31;
    for (int task = wid; task < 48; task += 8) {
        int o   = task / 12;
        int rem = task % 12;
        int h   = rem >> 1;
        int ch  = rem & 1;
        int c   = ch*32 + lane;
        int pp  = o*FIX_ + c*6 + h;
        int g   = pp >> 9;
        const float4* pu4 = (const float4*)pu + (size_t)pp*2;
        float4 pl = __ldg(pu4), ph = __ldg(pu4 + 1);
        float* op = out + ((size_t)(b*H_ + h)*W_ + 4*t0 + o)*C_ + c;
        const float4* zb = (const float4*)(sZ + g*(TT*D_));
#pragma unroll 5
        for (int tl = 0; tl < TT; tl++) {
            float4 zl = zb[tl*2], zh = zb[tl*2 + 1];
            float s0 = zl.x*pl.x, s1 = zl.y*pl.y;
            s0 = fmaf(zl.z, pl.z, s0); s1 = fmaf(zl.w, pl.w, s1);
            s0 = fmaf(zh.x, ph.x, s0); s1 = fmaf(zh.y, ph.y, s1);
            s0 = fmaf(zh.z, ph.z, s0); s1 = fmaf(zh.w, ph.w, s1);
            op[(size_t)tl*4*C_] = s0 + s1;
        }
    }
}

// ---------------------------------------------------------------------------
// K5: final deterministic loss reduction.
// ---------------------------------------------------------------------------
__global__ void k_final(float* __restrict__ d_out) {
    __shared__ float s[512];
    int tid = threadIdx.x;
    float v = 0.f;
    for (int idx = tid; idx < RVQ_BLOCKS; idx += 512) v += g_partial[idx];
    s[tid] = v; __syncthreads();
    for (int off = 256; off > 0; off >>= 1) {
        if (tid < off) s[tid] += s[tid + off];
        __syncthreads();
    }
    if (tid == 0) {
        float loss = s[0] / (float)(G_ * B_ * T_ * D_);
        d_out[ZQ_SIZE + IDX_SIZE]     = loss;
        d_out[ZQ_SIZE + IDX_SIZE + 1] = loss;
    }
}

// ---------------------------------------------------------------------------
extern "C" void kernel_launch(void* const* d_in, const int* in_sizes, int n_in,
                              void* d_out, int out_size) {
    const float* z_e = (const float*)d_in[0];
    const float* pd  = (const float*)d_in[1];
    const float* pu  = (const float*)d_in[2];
    const float* cb  = (const float*)d_in[3];
    float* out = (float*)d_out;

    cudaFuncSetAttribute(k_down, cudaFuncAttributeMaxDynamicSharedMemorySize, K2_SMEM);

    k_norm<<<(G_*NVQ_*K_ + 255)/256, 256>>>(cb);
    k_down<<<B_*(T_/8), 256, K2_SMEM>>>(z_e, pd);
    k_rvq<<<RVQ_BLOCKS, 32>>>(out + ZQ_SIZE);
    k_up<<<B_*(T_/TT), 256>>>(pu, out);
    k_final<<<1, 512>>>(out);
}